// round 16
// baseline (speedup 1.0000x reference)
#include <cuda_runtime.h>
#include <math.h>
#include <stdint.h>

#define BGR 32768
#define NPG 54
#define EPG 144
#define GLOB 10
#define F0 8
#define F1 16
#define F2 4
#define CAT 226   /* 54*4 + 10 */
#define H1 128
#define BM 64
#define WPG 4     /* graphs (warps) per gconv CTA */
#define KPAD 240  /* 226 padded to 15 x 16 */
#define BKH 16

// Scratch: concat([embeds, g]) per graph, [B, 226]
__device__ float g_emb[BGR * CAT];

// ---- tf32 helpers ----
__device__ __forceinline__ uint32_t f2tf32(float a) {
    uint32_t r; asm("cvt.rna.tf32.f32 %0, %1;" : "=r"(r) : "f"(a)); return r;
}
__device__ __forceinline__ void mma_tf32(float* c, const uint32_t* a, const uint32_t* b) {
    asm volatile(
        "mma.sync.aligned.m16n8k8.row.col.f32.tf32.tf32.f32 "
        "{%0,%1,%2,%3}, {%4,%5,%6,%7}, {%8,%9}, {%0,%1,%2,%3};"
        : "+f"(c[0]), "+f"(c[1]), "+f"(c[2]), "+f"(c[3])
        : "r"(a[0]), "r"(a[1]), "r"(a[2]), "r"(a[3]), "r"(b[0]), "r"(b[1]));
}

// ---------------------------------------------------------------------------
// Kernel 1: warp-per-graph GraphConv x2 (+ ReLU) + global MLP.  (R12, proven)
// ---------------------------------------------------------------------------
__global__ void __launch_bounds__(128) gconv_kernel(
    const float* __restrict__ x,
    const int*   __restrict__ eidx,    // [2, E]
    const float* __restrict__ eattr,
    const float* __restrict__ gfeat,
    const float* __restrict__ W_rel1, const float* __restrict__ b1,
    const float* __restrict__ W_root1,
    const float* __restrict__ W_rel2, const float* __restrict__ b2,
    const float* __restrict__ W_root2,
    const float* __restrict__ Wg1, const float* __restrict__ bg1,
    const float* __restrict__ Wg2, const float* __restrict__ bg2,
    const float* __restrict__ Wg3, const float* __restrict__ bg3)
{
    const int tid  = threadIdx.x;
    const int w    = tid >> 5;
    const int lane = tid & 31;
    const int b    = blockIdx.x * WPG + w;

    __shared__ float4 sx4[WPG][NPG * 2];
    __shared__ float4 sh4[WPG][NPG * 4];
    __shared__ float4 sagg4[WPG][NPG * 2];
    __shared__ float2 sedge[WPG][EPG];
    __shared__ int    soff[WPG][NPG + 2];
    __shared__ int    scur[WPG][NPG];
    __shared__ float  wr1[F0 * F1], wrt1[F0 * F1], sb1[F1];
    __shared__ float  wr2[F1 * F2], wrt2[F1 * F2], sb2[F2];
    __shared__ float  wg1[GLOB * 8], wg2[64], wg3[80];
    __shared__ float  sbg1[8], sbg2[8], sbg3[GLOB];

    float* sattr_u = (float*)sagg4[w];
    short* ssrc_u  = (short*)(sattr_u + EPG);
    short* sdst_u  = ssrc_u + EPG;
    float* shfp    = (float*)sh4[w];

    if (tid < F0 * F1) { wr1[tid] = W_rel1[tid]; wrt1[tid] = W_root1[tid]; }
    if (tid < F1 * F2) { wr2[tid] = W_rel2[tid]; wrt2[tid] = W_root2[tid]; }
    if (tid < F1) sb1[tid] = b1[tid];
    if (tid < F2) sb2[tid] = b2[tid];
    if (tid < GLOB * 8) wg1[tid] = Wg1[tid];
    if (tid < 64) wg2[tid] = Wg2[tid];
    if (tid < 80) wg3[tid] = Wg3[tid];
    if (tid < 8)  { sbg1[tid] = bg1[tid]; sbg2[tid] = bg2[tid]; }
    if (tid < GLOB) sbg3[tid] = bg3[tid];

    {
        const float4* xg = (const float4*)(x + (size_t)b * (NPG * F0));
        #pragma unroll
        for (int i = lane; i < NPG * 2; i += 32) sx4[w][i] = xg[i];
    }
    {
        const int*   srcg = eidx + (size_t)b * EPG;
        const int*   dstg = eidx + (size_t)BGR * EPG + (size_t)b * EPG;
        const float* ag   = eattr + (size_t)b * EPG;
        const int base = b * NPG;
        #pragma unroll
        for (int e = lane; e < EPG; e += 32) {
            sattr_u[e] = ag[e];
            ssrc_u[e]  = (short)(srcg[e] - base);
            sdst_u[e]  = (short)(dstg[e] - base);
        }
    }
    for (int i = lane; i < NPG; i += 32) scur[w][i] = 0;
    __syncthreads();

    #pragma unroll
    for (int e = lane; e < EPG; e += 32) atomicAdd(&scur[w][sdst_u[e]], 1);
    __syncwarp();

    {
        int c0 = 0, c1 = 0;
        if (lane < 27) { c0 = scur[w][2 * lane]; c1 = scur[w][2 * lane + 1]; }
        int s = c0 + c1, incl = s;
        #pragma unroll
        for (int o = 1; o < 32; o <<= 1) {
            int u = __shfl_up_sync(0xffffffffu, incl, o);
            if (lane >= o) incl += u;
        }
        int excl = incl - s;
        if (lane < 27) { soff[w][2 * lane] = excl; soff[w][2 * lane + 1] = excl + c0; }
        if (lane == 26) soff[w][NPG] = incl;
    }
    __syncwarp();
    for (int i = lane; i < NPG; i += 32) scur[w][i] = soff[w][i];
    __syncwarp();

    #pragma unroll
    for (int e = lane; e < EPG; e += 32) {
        int slot = atomicAdd(&scur[w][sdst_u[e]], 1);
        float2 pe; pe.x = sattr_u[e]; pe.y = __int_as_float((int)ssrc_u[e]);
        sedge[w][slot] = pe;
    }

    {
        float gv = (lane < GLOB) ? gfeat[(size_t)b * GLOB + lane] : 0.f;
        float v1 = (lane < 8) ? sbg1[lane] : 0.f;
        #pragma unroll
        for (int i = 0; i < GLOB; i++) {
            float gi = __shfl_sync(0xffffffffu, gv, i);
            if (lane < 8) v1 += gi * wg1[i * 8 + lane];
        }
        v1 = fmaxf(v1, 0.f);
        float v2 = (lane < 8) ? sbg2[lane] : 0.f;
        #pragma unroll
        for (int i = 0; i < 8; i++) {
            float vi = __shfl_sync(0xffffffffu, v1, i);
            if (lane < 8) v2 += vi * wg2[i * 8 + lane];
        }
        v2 = fmaxf(v2, 0.f);
        float v3 = (lane < GLOB) ? sbg3[lane] : 0.f;
        #pragma unroll
        for (int i = 0; i < 8; i++) {
            float vi = __shfl_sync(0xffffffffu, v2, i);
            if (lane < GLOB) v3 += vi * wg3[i * GLOB + lane];
        }
        if (lane < GLOB)
            g_emb[(size_t)b * CAT + NPG * F2 + lane] = fmaxf(v3, 0.f);
    }
    __syncwarp();

    #pragma unroll
    for (int it = lane; it < NPG * 2; it += 32) {
        int n = it >> 1, h = it & 1;
        float4 a = make_float4(0.f, 0.f, 0.f, 0.f);
        int k1 = soff[w][n + 1];
        for (int k = soff[w][n]; k < k1; k++) {
            float2 e = sedge[w][k];
            float4 xv = sx4[w][__float_as_int(e.y) * 2 + h];
            a.x += e.x * xv.x; a.y += e.x * xv.y;
            a.z += e.x * xv.z; a.w += e.x * xv.w;
        }
        sagg4[w][it] = a;
    }
    __syncwarp();

    {
        const int j = lane & 15, g2 = lane >> 4;
        float wc[16];
        const float bj = sb1[j];
        #pragma unroll
        for (int i = 0; i < F0; i++) { wc[i] = wr1[i * F1 + j]; wc[8 + i] = wrt1[i * F1 + j]; }
        for (int n = g2; n < NPG; n += 2) {
            float4 a0 = sagg4[w][n * 2], a1 = sagg4[w][n * 2 + 1];
            float4 x0 = sx4[w][n * 2],  x1 = sx4[w][n * 2 + 1];
            float v = bj;
            v += a0.x * wc[0] + a0.y * wc[1] + a0.z * wc[2] + a0.w * wc[3];
            v += a1.x * wc[4] + a1.y * wc[5] + a1.z * wc[6] + a1.w * wc[7];
            v += x0.x * wc[8] + x0.y * wc[9] + x0.z * wc[10] + x0.w * wc[11];
            v += x1.x * wc[12] + x1.y * wc[13] + x1.z * wc[14] + x1.w * wc[15];
            shfp[n * F1 + j] = fmaxf(v, 0.f);
        }
    }
    __syncwarp();

    {
        const int c = lane & 3, g2 = lane >> 2;
        float wa[16], wb[16];
        #pragma unroll
        for (int j = 0; j < F1; j++) { wa[j] = wr2[j * F2 + c]; wb[j] = wrt2[j * F2 + c]; }
        const float bc = sb2[c];
        for (int n = g2; n < NPG; n += 8) {
            float tr = 0.f, rr = bc;
            #pragma unroll
            for (int q = 0; q < 4; q++) {
                float4 h = sh4[w][n * 4 + q];
                tr += h.x * wa[q * 4 + 0] + h.y * wa[q * 4 + 1]
                    + h.z * wa[q * 4 + 2] + h.w * wa[q * 4 + 3];
                rr += h.x * wb[q * 4 + 0] + h.y * wb[q * 4 + 1]
                    + h.z * wb[q * 4 + 2] + h.w * wb[q * 4 + 3];
            }
            ((float*)&sagg4[w][n])[c]       = tr;
            ((float*)&sagg4[w][NPG + n])[c] = rr;
        }
    }
    __syncwarp();

    for (int n = lane; n < NPG; n += 32) {
        float4 a = make_float4(0.f, 0.f, 0.f, 0.f);
        int k1 = soff[w][n + 1];
        for (int k = soff[w][n]; k < k1; k++) {
            float2 e = sedge[w][k];
            float4 tv = sagg4[w][__float_as_int(e.y)];
            a.x += e.x * tv.x; a.y += e.x * tv.y;
            a.z += e.x * tv.z; a.w += e.x * tv.w;
        }
        float4 r = sagg4[w][NPG + n];
        float2 lo = make_float2(fmaxf(a.x + r.x, 0.f), fmaxf(a.y + r.y, 0.f));
        float2 hi = make_float2(fmaxf(a.z + r.z, 0.f), fmaxf(a.w + r.w, 0.f));
        float* dst = g_emb + (size_t)b * CAT + n * F2;
        *(float2*)dst       = lo;
        *(float2*)(dst + 2) = hi;
    }
}

// ---------------------------------------------------------------------------
// Kernel 2: head via tf32 tensor cores (3xTF32 split for fp32-class accuracy)
// out = sigmoid( relu(A @ Wo1 + bo1) @ Wo2 + bo2 ),  A = g_emb [B, 226]
// 64 rows x 128 cols per CTA; 4 warps, each owns a 32-col slice, all rows.
// mma.sync.m16n8k8: acc += Ah*Bh + Ah*Bl + Al*Bh  (Al*Bl term ~1e-7, dropped)
// ---------------------------------------------------------------------------
__global__ void __launch_bounds__(128) head_kernel(
    const float* __restrict__ Wo1, const float* __restrict__ bo1,
    const float* __restrict__ Wo2, const float* __restrict__ bo2,
    float* __restrict__ out)
{
    __shared__ uint32_t Ah[BM][BKH + 4];     // row stride 20: conflict-free frags
    __shared__ uint32_t Al[BM][BKH + 4];
    __shared__ uint32_t Bh[BKH][H1 + 8];     // row stride 136: conflict-free frags
    __shared__ uint32_t Bl[BKH][H1 + 8];
    __shared__ float    red[BM][17];

    const int rowBase = blockIdx.x * BM;
    const int tid  = threadIdx.x;
    const int w    = tid >> 5;
    const int lane = tid & 31;
    const int gid  = lane >> 2, tig = lane & 3;
    const int n0   = w * 32;                  // this warp's col base

    float acc[4][4][4];                       // [m-tile][n-tile][c0..c3]
    #pragma unroll
    for (int m = 0; m < 4; m++)
        #pragma unroll
        for (int n = 0; n < 4; n++)
            #pragma unroll
            for (int r = 0; r < 4; r++) acc[m][n][r] = 0.f;

    const float* A = g_emb + (size_t)rowBase * CAT;

    for (int k0 = 0; k0 < KPAD; k0 += BKH) {
        // ---- load A 64x16 (float2 global; split hi/lo) ----
        {
            int row = tid >> 1, kq = (tid & 1) * 8;
            const float* src = A + (size_t)row * CAT + k0 + kq;
            #pragma unroll
            for (int i = 0; i < 4; i++) {
                int k = k0 + kq + 2 * i;
                float2 v = (k + 1 < CAT) ? *(const float2*)(src + 2 * i)
                         : (k < CAT ? make_float2(src[2 * i], 0.f)
                                    : make_float2(0.f, 0.f));
                uint32_t h0 = f2tf32(v.x);
                uint32_t h1 = f2tf32(v.y);
                Ah[row][kq + 2 * i]     = h0;
                Ah[row][kq + 2 * i + 1] = h1;
                Al[row][kq + 2 * i]     = f2tf32(v.x - __uint_as_float(h0));
                Al[row][kq + 2 * i + 1] = f2tf32(v.y - __uint_as_float(h1));
            }
        }
        // ---- load B 16x128 (float4 global; split hi/lo) ----
        {
            int kk = tid >> 3, colq = (tid & 7) * 16;
            int kg = k0 + kk;
            #pragma unroll
            for (int i = 0; i < 4; i++) {
                float4 v = (kg < CAT)
                    ? *(const float4*)&Wo1[(size_t)kg * H1 + colq + 4 * i]
                    : make_float4(0.f, 0.f, 0.f, 0.f);
                float vv[4] = {v.x, v.y, v.z, v.w};
                #pragma unroll
                for (int j = 0; j < 4; j++) {
                    uint32_t h = f2tf32(vv[j]);
                    Bh[kk][colq + 4 * i + j] = h;
                    Bl[kk][colq + 4 * i + j] = f2tf32(vv[j] - __uint_as_float(h));
                }
            }
        }
        __syncthreads();

        #pragma unroll
        for (int ks = 0; ks < BKH; ks += 8) {
            // B fragments for all 4 n-tiles
            uint32_t bh[4][2], bl[4][2];
            #pragma unroll
            for (int n = 0; n < 4; n++) {
                int col = n0 + n * 8 + gid;
                bh[n][0] = Bh[ks + tig][col];     bh[n][1] = Bh[ks + tig + 4][col];
                bl[n][0] = Bl[ks + tig][col];     bl[n][1] = Bl[ks + tig + 4][col];
            }
            #pragma unroll
            for (int m = 0; m < 4; m++) {
                int r0 = m * 16 + gid;
                uint32_t ah[4], al[4];
                ah[0] = Ah[r0][ks + tig];         ah[1] = Ah[r0 + 8][ks + tig];
                ah[2] = Ah[r0][ks + tig + 4];     ah[3] = Ah[r0 + 8][ks + tig + 4];
                al[0] = Al[r0][ks + tig];         al[1] = Al[r0 + 8][ks + tig];
                al[2] = Al[r0][ks + tig + 4];     al[3] = Al[r0 + 8][ks + tig + 4];
                #pragma unroll
                for (int n = 0; n < 4; n++) {
                    mma_tf32(acc[m][n], ah, bh[n]);
                    mma_tf32(acc[m][n], ah, bl[n]);
                    mma_tf32(acc[m][n], al, bh[n]);
                }
            }
        }
        __syncthreads();
    }

    // ---- epilogue: bias + relu + dot(Wo2) partials, cross-thread reduce ----
    float bb[8], w2[8];
    #pragma unroll
    for (int n = 0; n < 4; n++)
        #pragma unroll
        for (int j = 0; j < 2; j++) {
            int col = n0 + n * 8 + 2 * tig + j;
            bb[n * 2 + j] = bo1[col];
            w2[n * 2 + j] = Wo2[col];
        }
    #pragma unroll
    for (int m = 0; m < 4; m++) {
        float p0 = 0.f, p1 = 0.f;
        #pragma unroll
        for (int n = 0; n < 4; n++) {
            p0 += fmaxf(acc[m][n][0] + bb[n * 2], 0.f)     * w2[n * 2]
                + fmaxf(acc[m][n][1] + bb[n * 2 + 1], 0.f) * w2[n * 2 + 1];
            p1 += fmaxf(acc[m][n][2] + bb[n * 2], 0.f)     * w2[n * 2]
                + fmaxf(acc[m][n][3] + bb[n * 2 + 1], 0.f) * w2[n * 2 + 1];
        }
        red[m * 16 + gid][w * 4 + tig]     = p0;
        red[m * 16 + gid + 8][w * 4 + tig] = p1;
    }
    __syncthreads();
    if (tid < BM) {
        float s = bo2[0];
        #pragma unroll
        for (int t = 0; t < 16; t++) s += red[tid][t];
        out[rowBase + tid] = 1.f / (1.f + expf(-s));
    }
}

extern "C" void kernel_launch(void* const* d_in, const int* in_sizes, int n_in,
                              void* d_out, int out_size)
{
    const float* x       = (const float*)d_in[0];
    const int*   eidx    = (const int*)  d_in[1];
    const float* eattr   = (const float*)d_in[2];
    const float* gfeat   = (const float*)d_in[3];
    const float* W_rel1  = (const float*)d_in[4];
    const float* b1      = (const float*)d_in[5];
    const float* W_root1 = (const float*)d_in[6];
    const float* W_rel2  = (const float*)d_in[7];
    const float* b2      = (const float*)d_in[8];
    const float* W_root2 = (const float*)d_in[9];
    const float* Wg1     = (const float*)d_in[10];
    const float* bg1     = (const float*)d_in[11];
    const float* Wg2     = (const float*)d_in[12];
    const float* bg2     = (const float*)d_in[13];
    const float* Wg3     = (const float*)d_in[14];
    const float* bg3     = (const float*)d_in[15];
    const float* Wo1     = (const float*)d_in[16];
    const float* bo1     = (const float*)d_in[17];
    const float* Wo2     = (const float*)d_in[18];
    const float* bo2     = (const float*)d_in[19];
    float* out = (float*)d_out;

    gconv_kernel<<<BGR / WPG, 128>>>(x, eidx, eattr, gfeat,
                                     W_rel1, b1, W_root1,
                                     W_rel2, b2, W_root2,
                                     Wg1, bg1, Wg2, bg2, Wg3, bg3);
    head_kernel<<<BGR / BM, 128>>>(Wo1, bo1, Wo2, bo2, out);
}